// round 1
// baseline (speedup 1.0000x reference)
#include <cuda_runtime.h>
#include <cstdint>

#define NMS_B 8
#define NMS_N 10000
#define NMS_C 80
#define NMS_K 8
#define NMS_THR 0.5f
#define NMS_NEG -1e9f
#define FNEGMAX -3.402823466e38f

// Scratch (allocation-free rule: __device__ globals)
__device__ float  g_sel_score[NMS_B * NMS_C * NMS_K];
__device__ float4 g_sel_box  [NMS_B * NMS_C * NMS_K];
__device__ int    g_sel_valid[NMS_B * NMS_C * NMS_K];

// One block per (batch, class). Dense shared score array preserves original
// indices so argmax tie-breaking (lowest index wins, = jnp.argmax) is exact.
// Greedy NMS: pop global max, keep iff IoU<=0.5 vs all previously selected.
__global__ __launch_bounds__(256) void nms_per_class(
    const float* __restrict__ boxes, const float* __restrict__ scores)
{
    __shared__ float  s[NMS_N];          // 40 KB
    __shared__ float  rv[256];
    __shared__ int    ri[256];
    __shared__ int    nsel, done;
    __shared__ float4 selbox[NMS_K];
    __shared__ float  selsc[NMS_K];

    const int tid = threadIdx.x;
    const int blk = blockIdx.x;
    const int b = blk / NMS_C;
    const int c = blk % NMS_C;

    if (tid == 0) { nsel = 0; done = 0; }

    // Threshold + load class column (strided gather; hot in L2 across classes)
    const float* sp = scores + (size_t)b * NMS_N * NMS_C + c;
    for (int n = tid; n < NMS_N; n += 256) {
        float v = sp[(size_t)n * NMS_C];
        s[n] = (v > NMS_THR) ? v : NMS_NEG;
    }
    __syncthreads();

    const float4* bxp = reinterpret_cast<const float4*>(boxes) + (size_t)b * NMS_N;

    while (true) {
        // Block argmax with lowest-index tie-break
        float bv = FNEGMAX; int bi = NMS_N;
        for (int n = tid; n < NMS_N; n += 256) {
            float v = s[n];
            if (v > bv) { bv = v; bi = n; }   // strict > keeps lowest local index on ties
        }
        rv[tid] = bv; ri[tid] = bi;
        __syncthreads();
        #pragma unroll
        for (int st = 128; st > 0; st >>= 1) {
            if (tid < st) {
                float ov = rv[tid + st]; int oi = ri[tid + st];
                if (ov > rv[tid] || (ov == rv[tid] && oi < ri[tid])) {
                    rv[tid] = ov; ri[tid] = oi;
                }
            }
            __syncthreads();
        }

        if (tid == 0) {
            float mv = rv[0]; int mi = ri[0];
            if (mv <= NMS_THR) {
                done = 1;                    // nothing valid remains
            } else {
                s[mi] = FNEGMAX;             // pop
                float4 bb = bxp[mi];         // [y1,x1,y2,x2]
                bool ok = true;
                for (int j = 0; j < nsel; j++) {
                    float4 q = selbox[j];
                    float ih = fmaxf(fminf(bb.z, q.z) - fmaxf(bb.x, q.x), 0.0f);
                    float iw = fmaxf(fminf(bb.w, q.w) - fmaxf(bb.y, q.y), 0.0f);
                    float inter = ih * iw;
                    float uni = (bb.z - bb.x) * (bb.w - bb.y)
                              + (q.z - q.x) * (q.w - q.y) - inter;
                    if (inter / fmaxf(uni, 1e-9f) > 0.5f) { ok = false; break; }
                }
                if (ok) {
                    selbox[nsel] = bb;
                    selsc[nsel]  = mv;
                    nsel++;
                    if (nsel == NMS_K) done = 1;
                }
            }
        }
        __syncthreads();
        if (done) break;
    }

    if (tid < NMS_K) {
        int o = blk * NMS_K + tid;
        int v = (tid < nsel);
        g_sel_valid[o] = v;
        g_sel_score[o] = v ? selsc[tid] : NMS_NEG;
        float4 z = make_float4(0.f, 0.f, 0.f, 0.f);
        g_sel_box[o] = v ? selbox[tid] : z;
    }
}

// One block per batch: top-8 over 640 (class,k) masked scores with stable
// (lower-index-first) tie-break, matching lax.top_k; write all outputs.
// Output layout (f32): boxes[8][8][4] | scores[8][8] | classes[8][8] | valid[8]
__global__ __launch_bounds__(256) void topk_final(float* __restrict__ out)
{
    __shared__ float m[NMS_C * NMS_K];   // 640
    __shared__ float rv[256];
    __shared__ int   ri[256];
    __shared__ int   vcnt;

    const int tid = threadIdx.x;
    const int b   = blockIdx.x;

    for (int j = tid; j < NMS_C * NMS_K; j += 256)
        m[j] = g_sel_score[b * NMS_C * NMS_K + j];   // invalid already NEG
    if (tid == 0) vcnt = 0;
    __syncthreads();

    for (int k = 0; k < NMS_K; k++) {
        float bv = FNEGMAX; int bi = 1 << 30;
        for (int j = tid; j < NMS_C * NMS_K; j += 256) {
            float v = m[j];
            if (v > bv || (v == bv && j < bi)) { bv = v; bi = j; }
        }
        rv[tid] = bv; ri[tid] = bi;
        __syncthreads();
        #pragma unroll
        for (int st = 128; st > 0; st >>= 1) {
            if (tid < st) {
                float ov = rv[tid + st]; int oi = ri[tid + st];
                if (ov > rv[tid] || (ov == rv[tid] && oi < ri[tid])) {
                    rv[tid] = ov; ri[tid] = oi;
                }
            }
            __syncthreads();
        }
        if (tid == 0) {
            int p = ri[0];
            float sc = rv[0];
            m[p] = FNEGMAX;   // exclude from later picks
            int gi = b * NMS_C * NMS_K + p;
            int valid = g_sel_valid[gi];
            float4 bb = g_sel_box[gi];
            float* ob = out + b * 32 + k * 4;
            if (valid) {
                ob[0] = fminf(fmaxf(bb.x, 0.f), 1.f);
                ob[1] = fminf(fmaxf(bb.y, 0.f), 1.f);
                ob[2] = fminf(fmaxf(bb.z, 0.f), 1.f);
                ob[3] = fminf(fmaxf(bb.w, 0.f), 1.f);
                out[NMS_B * 32 + b * 8 + k] = sc;
                out[NMS_B * 40 + b * 8 + k] = (float)(p >> 3);   // class = idx // K
                vcnt++;
            } else {
                ob[0] = ob[1] = ob[2] = ob[3] = 0.f;
                out[NMS_B * 32 + b * 8 + k] = 0.f;
                out[NMS_B * 40 + b * 8 + k] = 0.f;
            }
        }
        __syncthreads();
    }
    if (tid == 0) out[NMS_B * 48 + b] = (float)vcnt;
}

extern "C" void kernel_launch(void* const* d_in, const int* in_sizes, int n_in,
                              void* d_out, int out_size)
{
    const float* boxes  = (const float*)d_in[0];
    const float* scores = (const float*)d_in[1];
    // Defensive: boxes has 320000 elems, scores 6.4M — swap if ordered otherwise.
    if (n_in >= 2 && in_sizes[0] > in_sizes[1]) {
        const float* t = boxes; boxes = scores; scores = t;
    }

    nms_per_class<<<NMS_B * NMS_C, 256>>>(boxes, scores);
    topk_final<<<NMS_B, 256>>>((float*)d_out);
}

// round 2
// speedup vs baseline: 1.1999x; 1.1999x over previous
#include <cuda_runtime.h>
#include <cstdint>

#define NMS_B 8
#define NMS_N 10000
#define NMS_C 80
#define NMS_K 8
#define SCORE_THR 0.5f
#define NMS_NEG -1e9f
#define FNEGMAX -3.402823466e38f
#define CAND 16

// Scratch (allocation-free rule: __device__ globals)
__device__ float  g_sel_score[NMS_B * NMS_C * NMS_K];
__device__ float4 g_sel_box  [NMS_B * NMS_C * NMS_K];
__device__ int    g_sel_valid[NMS_B * NMS_C * NMS_K];

// One block per (batch, class). Dense smem score array keeps original indices
// so argmax tie-break (lowest index = jnp.argmax) is exact. Greedy NMS via
// two-level argmax: 256 chunk maxima, chunk(t) = {t, t+256, ...}.
__global__ __launch_bounds__(256) void nms_per_class(
    const float* __restrict__ boxes, const float* __restrict__ scores)
{
    __shared__ float  s[NMS_N];           // 40 KB
    __shared__ float  cmax[256];
    __shared__ int    cidx[256];
    __shared__ int    sh_wi;
    __shared__ float  sh_wv;
    __shared__ int    cand_idx[CAND];
    __shared__ float  cand_sc[CAND];
    __shared__ float4 cand_box[CAND];
    __shared__ float4 selbox[NMS_K];
    __shared__ float  selsc[NMS_K];
    __shared__ int    sh_nsel, sh_done;

    const int tid  = threadIdx.x;
    const int lane = tid & 31;
    const int blk  = blockIdx.x;
    const int b    = blk / NMS_C;
    const int c    = blk % NMS_C;

    // ---- Phase 1: gather class column + threshold + per-chunk maxima ----
    const float* sp = scores + (size_t)b * NMS_N * NMS_C + c;
    float mv = FNEGMAX; int mi = 0;
    #pragma unroll
    for (int k = 0; k < 39; k++) {            // tid + k*256 <= 9983 < N always
        int n = tid + (k << 8);
        float v  = __ldg(sp + (size_t)n * NMS_C);
        float sv = (v > SCORE_THR) ? v : NMS_NEG;
        s[n] = sv;
        if (sv > mv) { mv = sv; mi = n; }     // strict > keeps lowest n (ties)
    }
    if (tid < NMS_N - 39 * 256) {             // tail: tid < 16
        int n = tid + 39 * 256;
        float v  = __ldg(sp + (size_t)n * NMS_C);
        float sv = (v > SCORE_THR) ? v : NMS_NEG;
        s[n] = sv;
        if (sv > mv) { mv = sv; mi = n; }
    }
    cmax[tid] = mv; cidx[tid] = mi;
    if (tid == 0) { sh_nsel = 0; sh_done = 0; }

    const float4* bxp = reinterpret_cast<const float4*>(boxes) + (size_t)b * NMS_N;

    // ---- Phase 2: batched greedy pops ----
    while (true) {
        int j;
        for (j = 0; j < CAND; j++) {
            __syncthreads();                  // cmax/cidx updates visible
            // warp 0: argmax over 256 (val, idx) chunk entries, lowest-idx ties
            if (tid < 32) {
                float bv = cmax[tid]; int bi = cidx[tid];
                #pragma unroll
                for (int k = 1; k < 8; k++) {
                    float v = cmax[tid + (k << 5)]; int i2 = cidx[tid + (k << 5)];
                    if (v > bv || (v == bv && i2 < bi)) { bv = v; bi = i2; }
                }
                #pragma unroll
                for (int off = 16; off > 0; off >>= 1) {
                    float ov = __shfl_down_sync(0xffffffffu, bv, off);
                    int   oi = __shfl_down_sync(0xffffffffu, bi, off);
                    if (ov > bv || (ov == bv && oi < bi)) { bv = ov; bi = oi; }
                }
                if (tid == 0) { sh_wi = bi; sh_wv = bv; }
            }
            __syncthreads();
            int wi = sh_wi; float wv = sh_wv;
            if (wv <= SCORE_THR) break;       // uniform: nothing valid remains
            if (tid == 0) { cand_idx[j] = wi; cand_sc[j] = wv; }

            // owner's warp: pop + rescan that single chunk (<=40 elems)
            int owner = wi & 255;
            if ((tid >> 5) == (owner >> 5)) {
                if (tid == owner) s[wi] = FNEGMAX;
                __syncwarp();
                float nmv = FNEGMAX; int nmi = owner;
                int n1 = owner + (lane << 8);             // k = lane (always < N)
                float v1 = s[n1];
                if (v1 > nmv) { nmv = v1; nmi = n1; }
                int n2 = owner + ((lane + 32) << 8);      // k = lane + 32
                if (n2 < NMS_N) {
                    float v2 = s[n2];
                    if (v2 > nmv) { nmv = v2; nmi = n2; }
                }
                #pragma unroll
                for (int off = 16; off > 0; off >>= 1) {
                    float ov = __shfl_down_sync(0xffffffffu, nmv, off);
                    int   oi = __shfl_down_sync(0xffffffffu, nmi, off);
                    if (ov > nmv || (ov == nmv && oi < nmi)) { nmv = ov; nmi = oi; }
                }
                if (lane == 0) { cmax[owner] = nmv; cidx[owner] = nmi; }
            }
        }
        const int ncand = j;                  // uniform across threads

        // parallel box fetch for the whole batch (one LDG round)
        __syncthreads();
        if (tid < ncand) cand_box[tid] = bxp[cand_idx[tid]];
        __syncthreads();

        // thread 0: greedy IoU walk (all operands in smem)
        if (tid == 0) {
            int nsel = sh_nsel;
            for (int q = 0; q < ncand && nsel < NMS_K; q++) {
                float4 bb = cand_box[q];
                bool ok = true;
                for (int t = 0; t < nsel; t++) {
                    float4 qq = selbox[t];
                    float ih = fmaxf(fminf(bb.z, qq.z) - fmaxf(bb.x, qq.x), 0.0f);
                    float iw = fmaxf(fminf(bb.w, qq.w) - fmaxf(bb.y, qq.y), 0.0f);
                    float inter = ih * iw;
                    float uni = (bb.z - bb.x) * (bb.w - bb.y)
                              + (qq.z - qq.x) * (qq.w - qq.y) - inter;
                    if (inter / fmaxf(uni, 1e-9f) > 0.5f) { ok = false; break; }
                }
                if (ok) { selbox[nsel] = bb; selsc[nsel] = cand_sc[q]; nsel++; }
            }
            sh_nsel = nsel;
            if (nsel == NMS_K || ncand < CAND) sh_done = 1;  // ncand<CAND => exhausted
        }
        __syncthreads();
        if (sh_done) break;
    }

    if (tid < NMS_K) {
        int o = blk * NMS_K + tid;
        int v = (tid < sh_nsel);
        g_sel_valid[o] = v;
        g_sel_score[o] = v ? selsc[tid] : NMS_NEG;
        float4 z = make_float4(0.f, 0.f, 0.f, 0.f);
        g_sel_box[o] = v ? selbox[tid] : z;
    }
}

// One block per batch: smem-resident top-8 over 640 (class,k) masked scores,
// stable lowest-index tie-break (= lax.top_k). Warp-0-only pop loop, no block
// barriers inside it.
// Output (f32): boxes[8][8][4] | scores[8][8] | classes[8][8] | valid[8]
__global__ __launch_bounds__(256) void topk_final(float* __restrict__ out)
{
    __shared__ float  sc[NMS_C * NMS_K];
    __shared__ float4 bx[NMS_C * NMS_K];
    __shared__ int    vd[NMS_C * NMS_K];

    const int tid = threadIdx.x;
    const int b   = blockIdx.x;
    const int base = b * NMS_C * NMS_K;

    for (int j = tid; j < NMS_C * NMS_K; j += 256) {
        sc[j] = g_sel_score[base + j];
        vd[j] = g_sel_valid[base + j];
        bx[j] = g_sel_box[base + j];
    }
    __syncthreads();

    if (tid < 32) {
        int vcnt = 0;
        for (int k = 0; k < NMS_K; k++) {
            float bv = FNEGMAX; int bi = 1 << 30;
            for (int j2 = tid; j2 < NMS_C * NMS_K; j2 += 32) {
                float v = sc[j2];
                if (v > bv || (v == bv && j2 < bi)) { bv = v; bi = j2; }
            }
            #pragma unroll
            for (int off = 16; off > 0; off >>= 1) {
                float ov = __shfl_down_sync(0xffffffffu, bv, off);
                int   oi = __shfl_down_sync(0xffffffffu, bi, off);
                if (ov > bv || (ov == bv && oi < bi)) { bv = ov; bi = oi; }
            }
            bi = __shfl_sync(0xffffffffu, bi, 0);
            bv = __shfl_sync(0xffffffffu, bv, 0);
            if (tid == 0) {
                sc[bi] = FNEGMAX;
                int valid = vd[bi];
                float4 bb = bx[bi];
                float* ob = out + b * 32 + k * 4;
                if (valid) {
                    ob[0] = fminf(fmaxf(bb.x, 0.f), 1.f);
                    ob[1] = fminf(fmaxf(bb.y, 0.f), 1.f);
                    ob[2] = fminf(fmaxf(bb.z, 0.f), 1.f);
                    ob[3] = fminf(fmaxf(bb.w, 0.f), 1.f);
                    out[NMS_B * 32 + b * 8 + k] = bv;
                    out[NMS_B * 40 + b * 8 + k] = (float)(bi >> 3);  // class = idx // K
                    vcnt++;
                } else {
                    ob[0] = ob[1] = ob[2] = ob[3] = 0.f;
                    out[NMS_B * 32 + b * 8 + k] = 0.f;
                    out[NMS_B * 40 + b * 8 + k] = 0.f;
                }
            }
            __syncwarp();   // sc[bi] kill visible to all lanes before next pop
        }
        if (tid == 0) out[NMS_B * 48 + b] = (float)vcnt;
    }
}

extern "C" void kernel_launch(void* const* d_in, const int* in_sizes, int n_in,
                              void* d_out, int out_size)
{
    const float* boxes  = (const float*)d_in[0];
    const float* scores = (const float*)d_in[1];
    if (n_in >= 2 && in_sizes[0] > in_sizes[1]) {   // defensive input order
        const float* t = boxes; boxes = scores; scores = t;
    }
    nms_per_class<<<NMS_B * NMS_C, 256>>>(boxes, scores);
    topk_final<<<NMS_B, 256>>>((float*)d_out);
}

// round 3
// speedup vs baseline: 1.8379x; 1.5317x over previous
#include <cuda_runtime.h>
#include <cstdint>

#define NMS_B 8
#define NMS_N 10000
#define NMS_C 80
#define NMS_K 8
#define SCORE_THR 0.5f
#define NMS_NEG -1e9f
#define FNEGMAX -3.402823466e38f
#define CAND 16
#define TP_TILE 128   // n-rows per transpose tile

// Scratch (allocation-free rule: __device__ globals)
__device__ float  g_scoresT[NMS_B * NMS_C * NMS_N];   // [B][C][N], thresholded
__device__ float  g_sel_score[NMS_B * NMS_C * NMS_K];
__device__ float4 g_sel_box  [NMS_B * NMS_C * NMS_K];
__device__ int    g_sel_valid[NMS_B * NMS_C * NMS_K];

// ---------------------------------------------------------------------------
// Pass 1: coalesced transpose [B,N,C] -> [B,C,N] with threshold fused.
// grid = (ceil(N/TP_TILE), B), block = 256. smem tile padded to kill conflicts.
// ---------------------------------------------------------------------------
__global__ __launch_bounds__(256) void transpose_scores(
    const float* __restrict__ scores)
{
    __shared__ float t[TP_TILE][NMS_C + 1];   // pad: stride 81 coprime w/ 32

    const int tid = threadIdx.x;
    const int n0  = blockIdx.x * TP_TILE;
    const int b   = blockIdx.y;
    const int nrows = min(TP_TILE, NMS_N - n0);
    const int nelem = nrows * NMS_C;

    const float* sp = scores + (size_t)b * NMS_N * NMS_C + (size_t)n0 * NMS_C;
    for (int i = tid; i < nelem; i += 256) {
        float v = __ldg(sp + i);
        t[i / NMS_C][i % NMS_C] = (v > SCORE_THR) ? v : NMS_NEG;
    }
    __syncthreads();

    float* op = g_scoresT + (size_t)b * NMS_C * NMS_N + n0;
    for (int i = tid; i < NMS_C * nrows; i += 256) {
        int c = i / nrows, n = i % nrows;     // consecutive lanes -> consecutive n
        op[(size_t)c * NMS_N + n] = t[n][c];
    }
}

// ---------------------------------------------------------------------------
// Pass 2: one block per (batch, class). Contiguous float4 loads from scoresT.
// Two-level argmax (256 chunk maxima over float4 index space), batched pops.
// ---------------------------------------------------------------------------
__global__ __launch_bounds__(256) void nms_per_class(
    const float* __restrict__ boxes)
{
    __shared__ float  s[NMS_N];           // 40 KB, indexed by original n
    __shared__ float  cmax[256];
    __shared__ int    cidx[256];
    __shared__ int    sh_wi;
    __shared__ float  sh_wv;
    __shared__ int    cand_idx[CAND];
    __shared__ float  cand_sc[CAND];
    __shared__ float4 cand_box[CAND];
    __shared__ float4 selbox[NMS_K];
    __shared__ float  selsc[NMS_K];
    __shared__ int    sh_nsel, sh_done;

    const int tid  = threadIdx.x;
    const int lane = tid & 31;
    const int blk  = blockIdx.x;
    const int b    = blk / NMS_C;
    const int c    = blk % NMS_C;

    // ---- contiguous vector load + per-chunk maxima ----
    // float4 index idx4 = tid + k*256; chunk owner = idx4 & 255 = tid.
    const float4* sp4 = reinterpret_cast<const float4*>(
        g_scoresT + ((size_t)b * NMS_C + c) * NMS_N);
    float4* s4 = reinterpret_cast<float4*>(s);
    float mv = FNEGMAX; int mi = 0;
    #pragma unroll
    for (int k = 0; k < 10; k++) {            // 2500 float4 = 9*256 + 196
        int idx4 = tid + (k << 8);
        if (idx4 < 2500) {
            float4 v = __ldg(sp4 + idx4);
            s4[idx4] = v;
            int n = idx4 << 2;                // ascending n, strict > => lowest n
            if (v.x > mv) { mv = v.x; mi = n; }
            if (v.y > mv) { mv = v.y; mi = n + 1; }
            if (v.z > mv) { mv = v.z; mi = n + 2; }
            if (v.w > mv) { mv = v.w; mi = n + 3; }
        }
    }
    cmax[tid] = mv; cidx[tid] = mi;
    if (tid == 0) { sh_nsel = 0; sh_done = 0; }

    const float4* bxp = reinterpret_cast<const float4*>(boxes) + (size_t)b * NMS_N;

    // ---- batched greedy pops ----
    while (true) {
        int j;
        for (j = 0; j < CAND; j++) {
            __syncthreads();
            if (tid < 32) {                   // warp-0 argmax over 256 chunks
                float bv = cmax[tid]; int bi = cidx[tid];
                #pragma unroll
                for (int k = 1; k < 8; k++) {
                    float v = cmax[tid + (k << 5)]; int i2 = cidx[tid + (k << 5)];
                    if (v > bv || (v == bv && i2 < bi)) { bv = v; bi = i2; }
                }
                #pragma unroll
                for (int off = 16; off > 0; off >>= 1) {
                    float ov = __shfl_down_sync(0xffffffffu, bv, off);
                    int   oi = __shfl_down_sync(0xffffffffu, bi, off);
                    if (ov > bv || (ov == bv && oi < bi)) { bv = ov; bi = oi; }
                }
                if (tid == 0) { sh_wi = bi; sh_wv = bv; }
            }
            __syncthreads();
            int wi = sh_wi; float wv = sh_wv;
            if (wv <= SCORE_THR) break;
            if (tid == 0) { cand_idx[j] = wi; cand_sc[j] = wv; }

            // owner's warp: pop + rescan chunk (<=40 elems: n = 4*owner + 1024k + q)
            int owner = (wi >> 2) & 255;
            if ((tid >> 5) == (owner >> 5)) {
                if (tid == owner) s[wi] = FNEGMAX;
                __syncwarp();
                int kcnt = (owner < 196) ? 10 : 9;     // idx4 = owner + 256k < 2500
                int cnt  = kcnt << 2;
                float nmv = FNEGMAX; int nmi = owner << 2;
                int e = lane;                          // e = 4k + q, ascending n
                if (e < cnt) {
                    int n = (owner << 2) + ((e >> 2) << 10) + (e & 3);
                    float v = s[n];
                    if (v > nmv) { nmv = v; nmi = n; }
                }
                e = lane + 32;
                if (e < cnt) {
                    int n = (owner << 2) + ((e >> 2) << 10) + (e & 3);
                    float v = s[n];
                    if (v > nmv) { nmv = v; nmi = n; }
                }
                #pragma unroll
                for (int off = 16; off > 0; off >>= 1) {
                    float ov = __shfl_down_sync(0xffffffffu, nmv, off);
                    int   oi = __shfl_down_sync(0xffffffffu, nmi, off);
                    if (ov > nmv || (ov == nmv && oi < nmi)) { nmv = ov; nmi = oi; }
                }
                if (lane == 0) { cmax[owner] = nmv; cidx[owner] = nmi; }
            }
        }
        const int ncand = j;

        __syncthreads();
        if (tid < ncand) cand_box[tid] = __ldg(bxp + cand_idx[tid]);
        __syncthreads();

        if (tid == 0) {                       // greedy IoU walk, smem-only
            int nsel = sh_nsel;
            for (int q = 0; q < ncand && nsel < NMS_K; q++) {
                float4 bb = cand_box[q];
                bool ok = true;
                for (int t = 0; t < nsel; t++) {
                    float4 qq = selbox[t];
                    float ih = fmaxf(fminf(bb.z, qq.z) - fmaxf(bb.x, qq.x), 0.0f);
                    float iw = fmaxf(fminf(bb.w, qq.w) - fmaxf(bb.y, qq.y), 0.0f);
                    float inter = ih * iw;
                    float uni = (bb.z - bb.x) * (bb.w - bb.y)
                              + (qq.z - qq.x) * (qq.w - qq.y) - inter;
                    if (inter / fmaxf(uni, 1e-9f) > 0.5f) { ok = false; break; }
                }
                if (ok) { selbox[nsel] = bb; selsc[nsel] = cand_sc[q]; nsel++; }
            }
            sh_nsel = nsel;
            if (nsel == NMS_K || ncand < CAND) sh_done = 1;
        }
        __syncthreads();
        if (sh_done) break;
    }

    if (tid < NMS_K) {
        int o = blk * NMS_K + tid;
        int v = (tid < sh_nsel);
        g_sel_valid[o] = v;
        g_sel_score[o] = v ? selsc[tid] : NMS_NEG;
        float4 z = make_float4(0.f, 0.f, 0.f, 0.f);
        g_sel_box[o] = v ? selbox[tid] : z;
    }
}

// ---------------------------------------------------------------------------
// Pass 3: single block, warp w = batch w. Top-8 over 640 (class,k) scores with
// stable lowest-index tie-break (= lax.top_k). No block barriers in pop loop.
// Output (f32): boxes[8][8][4] | scores[8][8] | classes[8][8] | valid[8]
// ---------------------------------------------------------------------------
__global__ __launch_bounds__(256) void topk_final(float* __restrict__ out)
{
    __shared__ float sc[NMS_B][NMS_C * NMS_K];

    const int tid  = threadIdx.x;
    const int b    = tid >> 5;        // warp = batch
    const int lane = tid & 31;
    const int base = b * NMS_C * NMS_K;

    for (int j = lane; j < NMS_C * NMS_K; j += 32)
        sc[b][j] = g_sel_score[base + j];
    __syncwarp();

    int vcnt = 0;
    for (int k = 0; k < NMS_K; k++) {
        float bv = FNEGMAX; int bi = 1 << 30;
        #pragma unroll
        for (int q = 0; q < 20; q++) {          // 640 = 20*32
            int j2 = lane + (q << 5);
            float v = sc[b][j2];
            if (v > bv || (v == bv && j2 < bi)) { bv = v; bi = j2; }
        }
        #pragma unroll
        for (int off = 16; off > 0; off >>= 1) {
            float ov = __shfl_down_sync(0xffffffffu, bv, off);
            int   oi = __shfl_down_sync(0xffffffffu, bi, off);
            if (ov > bv || (ov == bv && oi < bi)) { bv = ov; bi = oi; }
        }
        bi = __shfl_sync(0xffffffffu, bi, 0);
        bv = __shfl_sync(0xffffffffu, bv, 0);
        if (lane == 0) {
            sc[b][bi] = FNEGMAX;
            int gi = base + bi;
            int valid = g_sel_valid[gi];
            float4 bb = g_sel_box[gi];
            float* ob = out + b * 32 + k * 4;
            if (valid) {
                ob[0] = fminf(fmaxf(bb.x, 0.f), 1.f);
                ob[1] = fminf(fmaxf(bb.y, 0.f), 1.f);
                ob[2] = fminf(fmaxf(bb.z, 0.f), 1.f);
                ob[3] = fminf(fmaxf(bb.w, 0.f), 1.f);
                out[NMS_B * 32 + b * 8 + k] = bv;
                out[NMS_B * 40 + b * 8 + k] = (float)(bi >> 3);
                vcnt++;
            } else {
                ob[0] = ob[1] = ob[2] = ob[3] = 0.f;
                out[NMS_B * 32 + b * 8 + k] = 0.f;
                out[NMS_B * 40 + b * 8 + k] = 0.f;
            }
        }
        __syncwarp();
    }
    if (lane == 0) out[NMS_B * 48 + b] = (float)vcnt;
}

extern "C" void kernel_launch(void* const* d_in, const int* in_sizes, int n_in,
                              void* d_out, int out_size)
{
    const float* boxes  = (const float*)d_in[0];
    const float* scores = (const float*)d_in[1];
    if (n_in >= 2 && in_sizes[0] > in_sizes[1]) {   // defensive input order
        const float* t = boxes; boxes = scores; scores = t;
    }
    dim3 tg((NMS_N + TP_TILE - 1) / TP_TILE, NMS_B);
    transpose_scores<<<tg, 256>>>(scores);
    nms_per_class<<<NMS_B * NMS_C, 256>>>(boxes);
    topk_final<<<1, 256>>>((float*)d_out);
}

// round 4
// speedup vs baseline: 1.9134x; 1.0411x over previous
#include <cuda_runtime.h>
#include <cstdint>

#define NMS_B 8
#define NMS_N 10000
#define NMS_C 80
#define NMS_K 8
#define SCORE_THR 0.5f
#define NMS_NEG -1e9f
#define FNEGMAX -3.402823466e38f
#define CAND 16
#define TP_ROWS 64
#define N4 2500            // NMS_N / 4

// Scratch (allocation-free rule: __device__ globals)
__device__ float  g_scoresT[NMS_B * NMS_C * NMS_N];   // [B][C][N], raw scores
__device__ float  g_sel_score[NMS_B * NMS_C * NMS_K];
__device__ float4 g_sel_box  [NMS_B * NMS_C * NMS_K];
__device__ int    g_sel_valid[NMS_B * NMS_C * NMS_K];
__device__ int    g_done_count;

// ---------------------------------------------------------------------------
// Pass 1: vectorized transpose [B,N,C] -> [B,C,N]. LDG.128 in, STS.128 to a
// stride-84 smem tile, 4-scalar LDS gather -> STG.128 out (4 consecutive n).
// Tiles are 64 rows (tail tile = 16 rows; both give power-of-2 nrows/4).
// Also resets the completion counter for the fused-topk ticket.
// ---------------------------------------------------------------------------
__global__ __launch_bounds__(256) void transpose_scores(
    const float* __restrict__ scores)
{
    __shared__ float t[TP_ROWS * 84];       // 21.5 KB; 84 = 21 float4 per row

    const int tid = threadIdx.x;
    const int n0  = blockIdx.x * TP_ROWS;
    const int b   = blockIdx.y;
    if (tid == 0 && n0 == 0 && b == 0) g_done_count = 0;

    const int nrows = min(TP_ROWS, NMS_N - n0);   // 64 or 16

    const float4* sp4 = reinterpret_cast<const float4*>(
        scores + ((size_t)b * NMS_N + n0) * NMS_C);
    float4* t4 = reinterpret_cast<float4*>(t);
    const int nin = nrows * 20;                   // 20 float4 per 80-col row
    for (int i = tid; i < nin; i += 256) {
        int r = i / 20, c4 = i - r * 20;          // const-divisor -> mul/shift
        t4[r * 21 + c4] = __ldg(sp4 + i);
    }
    __syncthreads();

    const int nq  = nrows >> 2;                   // 16 or 4 (both pow2)
    const int sh  = (nrows == TP_ROWS) ? 4 : 2;
    const int msk = nq - 1;
    float4* op4 = reinterpret_cast<float4*>(g_scoresT)
                + (size_t)b * NMS_C * N4 + (n0 >> 2);
    const int nout = NMS_C * nq;
    for (int i = tid; i < nout; i += 256) {
        int c = i >> sh, n4 = i & msk;
        int n = n4 << 2;
        float4 v;
        v.x = t[(n + 0) * 84 + c];
        v.y = t[(n + 1) * 84 + c];
        v.z = t[(n + 2) * 84 + c];
        v.w = t[(n + 3) * 84 + c];
        op4[(size_t)c * N4 + n4] = v;
    }
}

// ---------------------------------------------------------------------------
// Pass 2: one block per (batch, class). All 256 threads do the contiguous
// float4 load + threshold + chunk maxima; then WARP 0 alone runs the batched
// greedy pop loop (no block barriers inside). The last block to finish (atomic
// ticket) runs the final per-batch top-8 inline (warp = batch).
// Output (f32): boxes[8][8][4] | scores[8][8] | classes[8][8] | valid[8]
// ---------------------------------------------------------------------------
__global__ __launch_bounds__(256) void nms_per_class(
    const float* __restrict__ boxes, float* __restrict__ out)
{
    __shared__ float  s[NMS_N];           // 40 KB; reused as topk buffer at end
    __shared__ float  cmax[256];
    __shared__ int    cidx[256];
    __shared__ int    cand_i[CAND];
    __shared__ float  cand_s[CAND];
    __shared__ float4 cand_b[CAND];
    __shared__ float4 selbox[NMS_K];
    __shared__ float  selsc[NMS_K];
    __shared__ int    sh_nsel;
    __shared__ int    sh_ticket;

    const int tid  = threadIdx.x;
    const int lane = tid & 31;
    const int blk  = blockIdx.x;
    const int b    = blk / NMS_C;
    const int c    = blk % NMS_C;

    // ---- cooperative load: contiguous float4, threshold fused, chunk maxima
    const float4* sp4 = reinterpret_cast<const float4*>(g_scoresT)
                      + ((size_t)b * NMS_C + c) * N4;
    float4* s4 = reinterpret_cast<float4*>(s);
    float mv = FNEGMAX; int mi = 0;
    #pragma unroll
    for (int k = 0; k < 10; k++) {                // 2500 = 9*256 + 196
        int idx4 = tid + (k << 8);
        if (idx4 < N4) {
            float4 v = __ldg(sp4 + idx4);
            v.x = (v.x > SCORE_THR) ? v.x : NMS_NEG;
            v.y = (v.y > SCORE_THR) ? v.y : NMS_NEG;
            v.z = (v.z > SCORE_THR) ? v.z : NMS_NEG;
            v.w = (v.w > SCORE_THR) ? v.w : NMS_NEG;
            s4[idx4] = v;
            int n = idx4 << 2;                    // ascending n; strict > => lowest
            if (v.x > mv) { mv = v.x; mi = n; }
            if (v.y > mv) { mv = v.y; mi = n + 1; }
            if (v.z > mv) { mv = v.z; mi = n + 2; }
            if (v.w > mv) { mv = v.w; mi = n + 3; }
        }
    }
    cmax[tid] = mv; cidx[tid] = mi;
    __syncthreads();

    // ---- warp 0: batched greedy pops, warp-sync only ----
    if (tid < 32) {
        const float4* bxp = reinterpret_cast<const float4*>(boxes)
                          + (size_t)b * NMS_N;
        int  nsel = 0;
        bool done = false;
        while (!done) {
            int j;
            for (j = 0; j < CAND; j++) {
                // argmax over 256 chunk entries, lowest-n tie-break
                float bv = cmax[lane]; int bi = cidx[lane];
                #pragma unroll
                for (int q = 1; q < 8; q++) {
                    int o = lane + (q << 5);
                    float v = cmax[o]; int i2 = cidx[o];
                    if (v > bv || (v == bv && i2 < bi)) { bv = v; bi = i2; }
                }
                #pragma unroll
                for (int off = 16; off > 0; off >>= 1) {
                    float ov = __shfl_down_sync(0xffffffffu, bv, off);
                    int   oi = __shfl_down_sync(0xffffffffu, bi, off);
                    if (ov > bv || (ov == bv && oi < bi)) { bv = ov; bi = oi; }
                }
                bv = __shfl_sync(0xffffffffu, bv, 0);
                bi = __shfl_sync(0xffffffffu, bi, 0);
                if (bv <= SCORE_THR) break;
                if (lane == 0) { cand_i[j] = bi; cand_s[j] = bv; s[bi] = FNEGMAX; }
                __syncwarp();

                // rescan the popped chunk (<=40 elems), warp-parallel
                int owner = (bi >> 2) & 255;
                int kcnt  = (owner < 196) ? 10 : 9;    // idx4 = owner + 256k < 2500
                int cnt   = kcnt << 2;
                float nmv = FNEGMAX; int nmi = owner << 2;
                if (lane < cnt) {
                    int n = (owner << 2) + ((lane >> 2) << 10) + (lane & 3);
                    float v = s[n];
                    if (v > nmv) { nmv = v; nmi = n; }
                }
                int e = lane + 32;
                if (e < cnt) {
                    int n = (owner << 2) + ((e >> 2) << 10) + (e & 3);
                    float v = s[n];
                    if (v > nmv) { nmv = v; nmi = n; }  // larger n; strict > ok
                }
                #pragma unroll
                for (int off = 16; off > 0; off >>= 1) {
                    float ov = __shfl_down_sync(0xffffffffu, nmv, off);
                    int   oi = __shfl_down_sync(0xffffffffu, nmi, off);
                    if (ov > nmv || (ov == nmv && oi < nmi)) { nmv = ov; nmi = oi; }
                }
                if (lane == 0) { cmax[owner] = nmv; cidx[owner] = nmi; }
                __syncwarp();
            }
            int ncand = j;

            if (lane < ncand) cand_b[lane] = __ldg(bxp + cand_i[lane]);
            __syncwarp();

            if (lane == 0) {              // greedy IoU walk, smem-only
                for (int q = 0; q < ncand && nsel < NMS_K; q++) {
                    float4 bb = cand_b[q];
                    bool ok = true;
                    for (int t2 = 0; t2 < nsel; t2++) {
                        float4 qq = selbox[t2];
                        float ih = fmaxf(fminf(bb.z, qq.z) - fmaxf(bb.x, qq.x), 0.0f);
                        float iw = fmaxf(fminf(bb.w, qq.w) - fmaxf(bb.y, qq.y), 0.0f);
                        float inter = ih * iw;
                        float uni = (bb.z - bb.x) * (bb.w - bb.y)
                                  + (qq.z - qq.x) * (qq.w - qq.y) - inter;
                        if (inter / fmaxf(uni, 1e-9f) > 0.5f) { ok = false; break; }
                    }
                    if (ok) { selbox[nsel] = bb; selsc[nsel] = cand_s[q]; nsel++; }
                }
                sh_nsel = nsel;
            }
            __syncwarp();
            nsel = sh_nsel;
            done = (nsel == NMS_K) || (ncand < CAND);  // ncand<CAND => exhausted
        }
    }
    __syncthreads();

    if (tid < NMS_K) {
        int o = blk * NMS_K + tid;
        int v = (tid < sh_nsel);
        g_sel_valid[o] = v;
        g_sel_score[o] = v ? selsc[tid] : NMS_NEG;
        float4 z = make_float4(0.f, 0.f, 0.f, 0.f);
        g_sel_box[o] = v ? selbox[tid] : z;
    }
    __threadfence();
    __syncthreads();
    if (tid == 0) sh_ticket = atomicAdd(&g_done_count, 1);
    __syncthreads();
    if (sh_ticket != NMS_B * NMS_C - 1) return;
    __threadfence();

    // ---- fused final top-8 (last block only): warp = batch ----
    float* sc = s;                         // reuse the 40 KB buffer
    const int wb   = tid >> 5;
    const int base = wb * NMS_C * NMS_K;
    for (int j2 = lane; j2 < NMS_C * NMS_K; j2 += 32)
        sc[wb * 640 + j2] = g_sel_score[base + j2];
    __syncwarp();

    int vcnt = 0;
    for (int k = 0; k < NMS_K; k++) {
        float bv = FNEGMAX; int bi = 1 << 30;
        #pragma unroll
        for (int q = 0; q < 20; q++) {            // 640 = 20*32
            int j2 = lane + (q << 5);
            float v = sc[wb * 640 + j2];
            if (v > bv || (v == bv && j2 < bi)) { bv = v; bi = j2; }
        }
        #pragma unroll
        for (int off = 16; off > 0; off >>= 1) {
            float ov = __shfl_down_sync(0xffffffffu, bv, off);
            int   oi = __shfl_down_sync(0xffffffffu, bi, off);
            if (ov > bv || (ov == bv && oi < bi)) { bv = ov; bi = oi; }
        }
        bi = __shfl_sync(0xffffffffu, bi, 0);
        bv = __shfl_sync(0xffffffffu, bv, 0);
        if (lane == 0) {
            sc[wb * 640 + bi] = FNEGMAX;
            int gi = base + bi;
            int valid = g_sel_valid[gi];
            float4 bb = g_sel_box[gi];
            float* ob = out + wb * 32 + k * 4;
            if (valid) {
                ob[0] = fminf(fmaxf(bb.x, 0.f), 1.f);
                ob[1] = fminf(fmaxf(bb.y, 0.f), 1.f);
                ob[2] = fminf(fmaxf(bb.z, 0.f), 1.f);
                ob[3] = fminf(fmaxf(bb.w, 0.f), 1.f);
                out[NMS_B * 32 + wb * 8 + k] = bv;
                out[NMS_B * 40 + wb * 8 + k] = (float)(bi >> 3);   // class = idx // K
                vcnt++;
            } else {
                ob[0] = ob[1] = ob[2] = ob[3] = 0.f;
                out[NMS_B * 32 + wb * 8 + k] = 0.f;
                out[NMS_B * 40 + wb * 8 + k] = 0.f;
            }
        }
        __syncwarp();
    }
    if (lane == 0) out[NMS_B * 48 + wb] = (float)vcnt;
}

extern "C" void kernel_launch(void* const* d_in, const int* in_sizes, int n_in,
                              void* d_out, int out_size)
{
    const float* boxes  = (const float*)d_in[0];
    const float* scores = (const float*)d_in[1];
    if (n_in >= 2 && in_sizes[0] > in_sizes[1]) {   // defensive input order
        const float* t = boxes; boxes = scores; scores = t;
    }
    dim3 tg((NMS_N + TP_ROWS - 1) / TP_ROWS, NMS_B);
    transpose_scores<<<tg, 256>>>(scores);
    nms_per_class<<<NMS_B * NMS_C, 256>>>(boxes, (float*)d_out);
}

// round 5
// speedup vs baseline: 2.1825x; 1.1406x over previous
#include <cuda_runtime.h>
#include <cstdint>

#define NMS_B 8
#define NMS_N 10000
#define NMS_C 80
#define NMS_K 8
#define SCORE_THR 0.5f
#define NMS_NEG -1e9f
#define FNEGMAX -3.402823466e38f
#define TP_ROWS 64
#define N4 2500            // NMS_N / 4

typedef unsigned long long u64;

// Scratch (allocation-free rule: __device__ globals)
__device__ float  g_scoresT[NMS_B * NMS_C * NMS_N];   // [B][C][N], raw scores
__device__ float  g_sel_score[NMS_B * NMS_C * NMS_K];
__device__ float4 g_sel_box  [NMS_B * NMS_C * NMS_K];
__device__ int    g_sel_valid[NMS_B * NMS_C * NMS_K];
__device__ int    g_done_count;

// key = (score_bits, N-n): max-key == (max score, lowest n). Scores kept only
// if > THR (then they are positive floats, so uint order == float order);
// below threshold -> 0, which doubles as the "exhausted" sentinel.
__device__ __forceinline__ u64 mkey(float v, int n) {
    return (v > SCORE_THR)
        ? ((((u64)__float_as_uint(v)) << 32) | (unsigned)(NMS_N - n))
        : 0ULL;
}

// ---------------------------------------------------------------------------
// Pass 1: vectorized transpose [B,N,C] -> [B,C,N]. LDG.128 in, STS.128 to a
// stride-84 smem tile, 4-scalar LDS gather -> STG.128 out. Resets the ticket.
// ---------------------------------------------------------------------------
__global__ __launch_bounds__(256) void transpose_scores(
    const float* __restrict__ scores)
{
    __shared__ float t[TP_ROWS * 84];       // 84 = 21 float4 per row

    const int tid = threadIdx.x;
    const int n0  = blockIdx.x * TP_ROWS;
    const int b   = blockIdx.y;
    if (tid == 0 && n0 == 0 && b == 0) g_done_count = 0;

    const int nrows = min(TP_ROWS, NMS_N - n0);   // 64 or 16

    const float4* sp4 = reinterpret_cast<const float4*>(
        scores + ((size_t)b * NMS_N + n0) * NMS_C);
    float4* t4 = reinterpret_cast<float4*>(t);
    const int nin = nrows * 20;                   // 20 float4 per 80-col row
    for (int i = tid; i < nin; i += 256) {
        int r = i / 20, c4 = i - r * 20;
        t4[r * 21 + c4] = __ldg(sp4 + i);
    }
    __syncthreads();

    const int nq  = nrows >> 2;                   // 16 or 4
    const int sh  = (nrows == TP_ROWS) ? 4 : 2;
    const int msk = nq - 1;
    float4* op4 = reinterpret_cast<float4*>(g_scoresT)
                + (size_t)b * NMS_C * N4 + (n0 >> 2);
    const int nout = NMS_C * nq;
    for (int i = tid; i < nout; i += 256) {
        int c = i >> sh, n4 = i & msk;
        int n = n4 << 2;
        float4 v;
        v.x = t[(n + 0) * 84 + c];
        v.y = t[(n + 1) * 84 + c];
        v.z = t[(n + 2) * 84 + c];
        v.w = t[(n + 3) * 84 + c];
        op4[(size_t)c * N4 + n4] = v;
    }
}

// ---------------------------------------------------------------------------
// Pass 2: one block per (batch, class). 256 threads load + build 256 u64
// chunk-max keys; warp 0 runs the pop loop with register-resident group
// supermaxima (lane g = max over chunks 8g..8g+7), u64 shfl argmax, per-pop
// box prefetch, and warp-parallel IoU. Last block (atomic ticket) runs the
// final per-batch top-8 inline.
// Output (f32): boxes[8][8][4] | scores[8][8] | classes[8][8] | valid[8]
// ---------------------------------------------------------------------------
__global__ __launch_bounds__(256) void nms_per_class(
    const float* __restrict__ boxes, float* __restrict__ out)
{
    __shared__ float  s[NMS_N];           // 40 KB; reused as topk buffer
    __shared__ u64    cmax64[256];
    __shared__ float4 selbox[NMS_K];
    __shared__ float  selsc[NMS_K];
    __shared__ int    sh_nsel;
    __shared__ int    sh_ticket;

    const int tid  = threadIdx.x;
    const int lane = tid & 31;
    const int blk  = blockIdx.x;
    const int b    = blk / NMS_C;
    const int c    = blk % NMS_C;

    // ---- cooperative load: contiguous float4, threshold + u64 chunk keys ----
    const float4* sp4 = reinterpret_cast<const float4*>(g_scoresT)
                      + ((size_t)b * NMS_C + c) * N4;
    float4* s4 = reinterpret_cast<float4*>(s);
    u64 km = 0;
    #pragma unroll
    for (int k = 0; k < 10; k++) {                // 2500 = 9*256 + 196
        int idx4 = tid + (k << 8);
        if (idx4 < N4) {
            float4 v = __ldg(sp4 + idx4);
            float4 w;
            w.x = (v.x > SCORE_THR) ? v.x : NMS_NEG;
            w.y = (v.y > SCORE_THR) ? v.y : NMS_NEG;
            w.z = (v.z > SCORE_THR) ? v.z : NMS_NEG;
            w.w = (v.w > SCORE_THR) ? v.w : NMS_NEG;
            s4[idx4] = w;
            int n = idx4 << 2;
            u64 k0 = mkey(v.x, n);     if (k0 > km) km = k0;
            u64 k1 = mkey(v.y, n + 1); if (k1 > km) km = k1;
            u64 k2 = mkey(v.z, n + 2); if (k2 > km) km = k2;
            u64 k3 = mkey(v.w, n + 3); if (k3 > km) km = k3;
        }
    }
    cmax64[tid] = km;
    __syncthreads();

    // ---- warp 0: pop loop ----
    if (tid < 32) {
        // register supermax: lane g = max over chunk group g (8 chunks)
        u64 sm = 0;
        #pragma unroll
        for (int i = 0; i < 8; i++) {
            u64 cv = cmax64[(lane << 3) + i];
            if (cv > sm) sm = cv;
        }

        const float4* bxp = reinterpret_cast<const float4*>(boxes)
                          + (size_t)b * NMS_N;
        int    nsel = 0;
        float4 myb;                       // per-lane prefetched candidate box
        float  mysc = 0.0f;
        bool   done = false;

        while (!done) {
            int npop = 0;
            for (int p = 0; p < NMS_K; p++) {
                // argmax: 5-level u64 shfl-max over 32 register supermaxima
                u64 kk = sm;
                #pragma unroll
                for (int off = 16; off > 0; off >>= 1) {
                    u64 ok = __shfl_down_sync(0xffffffffu, kk, off);
                    if (ok > kk) kk = ok;
                }
                kk = __shfl_sync(0xffffffffu, kk, 0);
                if ((unsigned)(kk >> 32) == 0u) break;   // exhausted
                int n = NMS_N - (int)(kk & 0xffffffffu);
                if (lane == p) {                          // record + prefetch box
                    mysc = __uint_as_float((unsigned)(kk >> 32));
                    myb  = __ldg(bxp + n);
                }
                if (lane == 0) s[n] = NMS_NEG;            // pop
                __syncwarp();

                // rescan the popped chunk (<=40 elems, 2 per lane)
                int owner = (n >> 2) & 255;
                int cnt   = ((owner < 196) ? 10 : 9) << 2;
                u64 nk = 0;
                if (lane < cnt) {
                    int nn = (owner << 2) + ((lane >> 2) << 10) + (lane & 3);
                    nk = mkey(s[nn], nn);
                }
                int e = lane + 32;
                if (e < cnt) {
                    int nn = (owner << 2) + ((e >> 2) << 10) + (e & 3);
                    u64 k2 = mkey(s[nn], nn);
                    if (k2 > nk) nk = k2;
                }
                #pragma unroll
                for (int off = 16; off > 0; off >>= 1) {
                    u64 ok = __shfl_down_sync(0xffffffffu, nk, off);
                    if (ok > nk) nk = ok;
                }
                if (lane == 0) cmax64[owner] = nk;
                __syncwarp();
                int g = owner >> 3;
                if (lane == g) {                          // refresh my supermax
                    u64 t2 = 0;
                    #pragma unroll
                    for (int i = 0; i < 8; i++) {
                        u64 cv = cmax64[(g << 3) + i];
                        if (cv > t2) t2 = cv;
                    }
                    sm = t2;
                }
                npop = p + 1;
            }
            __syncwarp();

            // IoU walk: candidate q (in pop order) vs selected[], warp-parallel
            for (int q = 0; q < npop && nsel < NMS_K; q++) {
                float4 bb;
                bb.x = __shfl_sync(0xffffffffu, myb.x, q);
                bb.y = __shfl_sync(0xffffffffu, myb.y, q);
                bb.z = __shfl_sync(0xffffffffu, myb.z, q);
                bb.w = __shfl_sync(0xffffffffu, myb.w, q);
                float scq = __shfl_sync(0xffffffffu, mysc, q);
                bool sup = false;
                if (lane < nsel) {
                    float4 qq = selbox[lane];
                    float ih = fmaxf(fminf(bb.z, qq.z) - fmaxf(bb.x, qq.x), 0.0f);
                    float iw = fmaxf(fminf(bb.w, qq.w) - fmaxf(bb.y, qq.y), 0.0f);
                    float inter = ih * iw;
                    float uni = (bb.z - bb.x) * (bb.w - bb.y)
                              + (qq.z - qq.x) * (qq.w - qq.y) - inter;
                    sup = inter / fmaxf(uni, 1e-9f) > 0.5f;
                }
                if (!__ballot_sync(0xffffffffu, sup)) {
                    if (lane == 0) { selbox[nsel] = bb; selsc[nsel] = scq; }
                    nsel++;                  // uniform across lanes
                    __syncwarp();            // selbox visible to next q
                }
            }
            done = (nsel == NMS_K) || (npop < NMS_K);   // npop<K => exhausted
        }
        if (lane == 0) sh_nsel = nsel;
    }
    __syncthreads();

    if (tid < NMS_K) {
        int o = blk * NMS_K + tid;
        int v = (tid < sh_nsel);
        g_sel_valid[o] = v;
        g_sel_score[o] = v ? selsc[tid] : NMS_NEG;
        float4 z = make_float4(0.f, 0.f, 0.f, 0.f);
        g_sel_box[o] = v ? selbox[tid] : z;
    }
    __threadfence();
    __syncthreads();
    if (tid == 0) sh_ticket = atomicAdd(&g_done_count, 1);
    __syncthreads();
    if (sh_ticket != NMS_B * NMS_C - 1) return;
    __threadfence();

    // ---- fused final top-8 (last block only): warp = batch ----
    float* sc = s;
    const int wb   = tid >> 5;
    const int base = wb * NMS_C * NMS_K;
    for (int j2 = lane; j2 < NMS_C * NMS_K; j2 += 32)
        sc[wb * 640 + j2] = g_sel_score[base + j2];
    __syncwarp();

    int vcnt = 0;
    for (int k = 0; k < NMS_K; k++) {
        float bv = FNEGMAX; int bi = 1 << 30;
        #pragma unroll
        for (int q = 0; q < 20; q++) {            // 640 = 20*32
            int j2 = lane + (q << 5);
            float v = sc[wb * 640 + j2];
            if (v > bv || (v == bv && j2 < bi)) { bv = v; bi = j2; }
        }
        #pragma unroll
        for (int off = 16; off > 0; off >>= 1) {
            float ov = __shfl_down_sync(0xffffffffu, bv, off);
            int   oi = __shfl_down_sync(0xffffffffu, bi, off);
            if (ov > bv || (ov == bv && oi < bi)) { bv = ov; bi = oi; }
        }
        bi = __shfl_sync(0xffffffffu, bi, 0);
        bv = __shfl_sync(0xffffffffu, bv, 0);
        if (lane == 0) {
            sc[wb * 640 + bi] = FNEGMAX;
            int gi = base + bi;
            int valid = g_sel_valid[gi];
            float4 bb = g_sel_box[gi];
            float* ob = out + wb * 32 + k * 4;
            if (valid) {
                ob[0] = fminf(fmaxf(bb.x, 0.f), 1.f);
                ob[1] = fminf(fmaxf(bb.y, 0.f), 1.f);
                ob[2] = fminf(fmaxf(bb.z, 0.f), 1.f);
                ob[3] = fminf(fmaxf(bb.w, 0.f), 1.f);
                out[NMS_B * 32 + wb * 8 + k] = bv;
                out[NMS_B * 40 + wb * 8 + k] = (float)(bi >> 3);   // class = idx // K
                vcnt++;
            } else {
                ob[0] = ob[1] = ob[2] = ob[3] = 0.f;
                out[NMS_B * 32 + wb * 8 + k] = 0.f;
                out[NMS_B * 40 + wb * 8 + k] = 0.f;
            }
        }
        __syncwarp();
    }
    if (lane == 0) out[NMS_B * 48 + wb] = (float)vcnt;
}

extern "C" void kernel_launch(void* const* d_in, const int* in_sizes, int n_in,
                              void* d_out, int out_size)
{
    const float* boxes  = (const float*)d_in[0];
    const float* scores = (const float*)d_in[1];
    if (n_in >= 2 && in_sizes[0] > in_sizes[1]) {   // defensive input order
        const float* t = boxes; boxes = scores; scores = t;
    }
    dim3 tg((NMS_N + TP_ROWS - 1) / TP_ROWS, NMS_B);
    transpose_scores<<<tg, 256>>>(scores);
    nms_per_class<<<NMS_B * NMS_C, 256>>>(boxes, (float*)d_out);
}